// round 1
// baseline (speedup 1.0000x reference)
#include <cuda_runtime.h>
#include <math.h>

// Problem shapes
#define NB 256            // batch
#define NF 4              // frames
#define PIX 37632         // 3*112*112 floats per frame
#define PIX4 9408         // float4 per frame
#define BPB 8             // blocks per batch (img kernel)
#define TPB 256           // threads per block (img kernel)

// Scratch (device globals — no allocation allowed)
__device__ float g_diffsq[NB * 3];
__device__ int   g_neq[NB * 3];

__global__ void zero_kernel(float* __restrict__ out) {
    int i = blockIdx.x * blockDim.x + threadIdx.x;
    if (i < NB * 3) {
        g_diffsq[i] = 0.0f;
        g_neq[i] = 0;
    }
    if (i == 0) out[0] = 0.0f;
}

// One pass over img: per (batch, pair j in 0..2):
//   diffsq[j] = sum (img[j+1]-img[j])^2
//   neq[j]    = any(img[j+1] != img[0])
__global__ void img_kernel(const float4* __restrict__ img) {
    const int b = blockIdx.x >> 3;          // /BPB
    const int chunk = blockIdx.x & (BPB - 1);
    const float4* base = img + (size_t)b * (NF * PIX4);

    float s1 = 0.f, s2 = 0.f, s3 = 0.f;
    int n1 = 0, n2 = 0, n3 = 0;

    for (int i = chunk * TPB + threadIdx.x; i < PIX4; i += BPB * TPB) {
        float4 f0 = base[i];
        float4 f1 = base[PIX4 + i];
        float4 f2 = base[2 * PIX4 + i];
        float4 f3 = base[3 * PIX4 + i];

        float dx, dy, dz, dw;
        dx = f1.x - f0.x; dy = f1.y - f0.y; dz = f1.z - f0.z; dw = f1.w - f0.w;
        s1 += dx * dx + dy * dy + dz * dz + dw * dw;
        n1 |= (f1.x != f0.x) | (f1.y != f0.y) | (f1.z != f0.z) | (f1.w != f0.w);

        dx = f2.x - f1.x; dy = f2.y - f1.y; dz = f2.z - f1.z; dw = f2.w - f1.w;
        s2 += dx * dx + dy * dy + dz * dz + dw * dw;
        n2 |= (f2.x != f0.x) | (f2.y != f0.y) | (f2.z != f0.z) | (f2.w != f0.w);

        dx = f3.x - f2.x; dy = f3.y - f2.y; dz = f3.z - f2.z; dw = f3.w - f2.w;
        s3 += dx * dx + dy * dy + dz * dz + dw * dw;
        n3 |= (f3.x != f0.x) | (f3.y != f0.y) | (f3.z != f0.z) | (f3.w != f0.w);
    }

    // Block-wide OR for the neq flags
    n1 = __syncthreads_or(n1);
    n2 = __syncthreads_or(n2);
    n3 = __syncthreads_or(n3);

    // Warp-shuffle reduce the float sums
    #pragma unroll
    for (int off = 16; off; off >>= 1) {
        s1 += __shfl_down_sync(0xffffffffu, s1, off);
        s2 += __shfl_down_sync(0xffffffffu, s2, off);
        s3 += __shfl_down_sync(0xffffffffu, s3, off);
    }

    __shared__ float sm[3][TPB / 32];
    const int w = threadIdx.x >> 5;
    const int l = threadIdx.x & 31;
    if (l == 0) {
        sm[0][w] = s1;
        sm[1][w] = s2;
        sm[2][w] = s3;
    }
    __syncthreads();

    if (threadIdx.x < 3) {
        float s = 0.f;
        #pragma unroll
        for (int k = 0; k < TPB / 32; k++) s += sm[threadIdx.x][k];
        atomicAdd(&g_diffsq[b * 3 + threadIdx.x], s);
    }
    if (threadIdx.x == 0) {
        if (n1) atomicOr(&g_neq[b * 3 + 0], 1);
        if (n2) atomicOr(&g_neq[b * 3 + 1], 1);
        if (n3) atomicOr(&g_neq[b * 3 + 2], 1);
    }
}

// Per-batch feat dots/norms + scalar epilogue.
// out[0] = mean(penalty) (atomically accumulated), out[1+b] = weight[b]
__global__ void finalize_kernel(const float* __restrict__ feat,
                                const float* __restrict__ feat_norm,
                                float* __restrict__ out) {
    const int b = blockIdx.x;
    const float* fb = feat + (size_t)b * (NF * 512);

    float n0 = 0.f, n1 = 0.f, n2 = 0.f, n3 = 0.f;
    float d01 = 0.f, d12 = 0.f, d23 = 0.f;

    for (int i = threadIdx.x; i < 512; i += 128) {
        float a = fb[i];
        float c = fb[512 + i];
        float d = fb[1024 + i];
        float e = fb[1536 + i];
        n0 += a * a; n1 += c * c; n2 += d * d; n3 += e * e;
        d01 += a * c; d12 += c * d; d23 += d * e;
    }

    #pragma unroll
    for (int off = 16; off; off >>= 1) {
        n0  += __shfl_down_sync(0xffffffffu, n0,  off);
        n1  += __shfl_down_sync(0xffffffffu, n1,  off);
        n2  += __shfl_down_sync(0xffffffffu, n2,  off);
        n3  += __shfl_down_sync(0xffffffffu, n3,  off);
        d01 += __shfl_down_sync(0xffffffffu, d01, off);
        d12 += __shfl_down_sync(0xffffffffu, d12, off);
        d23 += __shfl_down_sync(0xffffffffu, d23, off);
    }

    __shared__ float sm[7][4];
    const int w = threadIdx.x >> 5;
    const int l = threadIdx.x & 31;
    if (l == 0) {
        sm[0][w] = n0;  sm[1][w] = n1;  sm[2][w] = n2;  sm[3][w] = n3;
        sm[4][w] = d01; sm[5][w] = d12; sm[6][w] = d23;
    }
    __syncthreads();

    if (threadIdx.x == 0) {
        float v[7];
        #pragma unroll
        for (int j = 0; j < 7; j++)
            v[j] = sm[j][0] + sm[j][1] + sm[j][2] + sm[j][3];

        float na[4];
        #pragma unroll
        for (int j = 0; j < 4; j++)
            na[j] = fmaxf(sqrtf(v[j]), 1e-8f);

        const float fn0 = feat_norm[b * NF];   // feat_norm[b,0,0]
        const bool cond = fn0 > 0.0f;          // TAO = 0
        const float wgt = 1.0f / (expf(fn0) + 1e-10f);

        float pen = 0.0f;
        #pragma unroll
        for (int j = 0; j < 3; j++) {
            float cosv = v[4 + j] / (na[j] * na[j + 1]);
            float img_diff = sqrtf(g_diffsq[b * 3 + j]) + 1e-10f;
            float ratio = (1.0f - cosv) / img_diff;   // LIP = 0
            float term = fmaxf(ratio, 0.0f) * wgt;    // SQUARED = false
            if (cond && g_neq[b * 3 + j]) pen += term;
        }

        atomicAdd(&out[0], pen * (1.0f / (float)NB));
        out[1 + b] = cond ? wgt : 0.0f;
    }
}

extern "C" void kernel_launch(void* const* d_in, const int* in_sizes, int n_in,
                              void* d_out, int out_size) {
    const float* img = (const float*)d_in[0];
    const float* feat = (const float*)d_in[1];
    const float* feat_norm = (const float*)d_in[2];
    float* out = (float*)d_out;

    zero_kernel<<<1, 1024>>>(out);
    img_kernel<<<NB * BPB, TPB>>>((const float4*)img);
    finalize_kernel<<<NB, 128>>>(feat, feat_norm, out);
}

// round 3
// speedup vs baseline: 1.0410x; 1.0410x over previous
#include <cuda_runtime.h>
#include <math.h>

// Shapes
#define NB 256            // batch
#define NF 4              // frames
#define PIX4 9408         // float4 per frame (3*112*112/4)
#define TILES_PER_B 4
#define NTILES (NB * TILES_PER_B)       // 1024 img tiles
#define TILE4 (PIX4 / TILES_PER_B)      // 2352 float4 per tile
#define TPB 256
#define NBLOCKS (NB + NTILES)           // 256 feat blocks + 1024 img blocks

// Scratch: written exactly once per slot per launch — no zeroing needed.
__device__ float g_part[NTILES * 3];    // per-tile squared-diff partials
__device__ int   g_neqp[NTILES * 3];    // per-tile any-neq flags
__device__ float g_cos[NB * 3];         // per-batch cosine similarities
__device__ int   g_ctr;                 // zero at process start; reset by epilogue

__global__ void fused_kernel(const float4* __restrict__ img,
                             const float* __restrict__ feat,
                             const float* __restrict__ feat_norm,
                             float* __restrict__ out) {
    __shared__ float sm7[7][TPB / 32];
    __shared__ float smr[TPB / 32];
    __shared__ int   s_last;

    const int w = threadIdx.x >> 5;
    const int l = threadIdx.x & 31;

    if (blockIdx.x < NB) {
        // ---------------- feat block: per-batch norms/dots/cos + weight ----
        const int b = blockIdx.x;
        const float* fb = feat + (size_t)b * (NF * 512);

        float n0 = 0.f, n1 = 0.f, n2 = 0.f, n3 = 0.f;
        float d01 = 0.f, d12 = 0.f, d23 = 0.f;
        #pragma unroll
        for (int k = 0; k < 2; k++) {
            int i = threadIdx.x + k * TPB;
            float a = fb[i];
            float c = fb[512 + i];
            float d = fb[1024 + i];
            float e = fb[1536 + i];
            n0 += a * a; n1 += c * c; n2 += d * d; n3 += e * e;
            d01 += a * c; d12 += c * d; d23 += d * e;
        }
        #pragma unroll
        for (int off = 16; off; off >>= 1) {
            n0  += __shfl_down_sync(0xffffffffu, n0,  off);
            n1  += __shfl_down_sync(0xffffffffu, n1,  off);
            n2  += __shfl_down_sync(0xffffffffu, n2,  off);
            n3  += __shfl_down_sync(0xffffffffu, n3,  off);
            d01 += __shfl_down_sync(0xffffffffu, d01, off);
            d12 += __shfl_down_sync(0xffffffffu, d12, off);
            d23 += __shfl_down_sync(0xffffffffu, d23, off);
        }
        if (l == 0) {
            sm7[0][w] = n0;  sm7[1][w] = n1;  sm7[2][w] = n2;  sm7[3][w] = n3;
            sm7[4][w] = d01; sm7[5][w] = d12; sm7[6][w] = d23;
        }
        __syncthreads();
        if (threadIdx.x == 0) {
            float v[7];
            #pragma unroll
            for (int j = 0; j < 7; j++) {
                float s = 0.f;
                #pragma unroll
                for (int k = 0; k < TPB / 32; k++) s += sm7[j][k];
                v[j] = s;
            }
            float na[4];
            #pragma unroll
            for (int j = 0; j < 4; j++) na[j] = fmaxf(sqrtf(v[j]), 1e-8f);
            #pragma unroll
            for (int j = 0; j < 3; j++)
                g_cos[b * 3 + j] = v[4 + j] / (na[j] * na[j + 1]);

            const float fn0 = feat_norm[b * NF];     // feat_norm[b,0,0]
            const bool cond = fn0 > 0.0f;            // TAO = 0
            const float wgt = 1.0f / (expf(fn0) + 1e-10f);
            out[1 + b] = cond ? wgt : 0.0f;          // wgt>0 always, so this also encodes cond
        }
    } else {
        // ---------------- img tile block: squared diffs + neq flags --------
        const int t = blockIdx.x - NB;               // tile index
        const int b = t >> 2;
        const int chunk = t & 3;
        const float4* base = img + (size_t)b * (NF * PIX4);

        float s1 = 0.f, s2 = 0.f, s3 = 0.f;
        int nq1 = 0, nq2 = 0, nq3 = 0;
        const int end = (chunk + 1) * TILE4;
        for (int i = chunk * TILE4 + threadIdx.x; i < end; i += TPB) {
            float4 f0 = base[i];
            float4 f1 = base[PIX4 + i];
            float4 f2 = base[2 * PIX4 + i];
            float4 f3 = base[3 * PIX4 + i];

            float dx, dy, dz, dw;
            dx = f1.x - f0.x; dy = f1.y - f0.y; dz = f1.z - f0.z; dw = f1.w - f0.w;
            s1 += dx * dx + dy * dy + dz * dz + dw * dw;
            nq1 |= (f1.x != f0.x) | (f1.y != f0.y) | (f1.z != f0.z) | (f1.w != f0.w);

            dx = f2.x - f1.x; dy = f2.y - f1.y; dz = f2.z - f1.z; dw = f2.w - f1.w;
            s2 += dx * dx + dy * dy + dz * dz + dw * dw;
            nq2 |= (f2.x != f0.x) | (f2.y != f0.y) | (f2.z != f0.z) | (f2.w != f0.w);

            dx = f3.x - f2.x; dy = f3.y - f2.y; dz = f3.z - f2.z; dw = f3.w - f2.w;
            s3 += dx * dx + dy * dy + dz * dz + dw * dw;
            nq3 |= (f3.x != f0.x) | (f3.y != f0.y) | (f3.z != f0.z) | (f3.w != f0.w);
        }

        nq1 = __syncthreads_or(nq1);
        nq2 = __syncthreads_or(nq2);
        nq3 = __syncthreads_or(nq3);

        #pragma unroll
        for (int off = 16; off; off >>= 1) {
            s1 += __shfl_down_sync(0xffffffffu, s1, off);
            s2 += __shfl_down_sync(0xffffffffu, s2, off);
            s3 += __shfl_down_sync(0xffffffffu, s3, off);
        }
        if (l == 0) { sm7[0][w] = s1; sm7[1][w] = s2; sm7[2][w] = s3; }
        __syncthreads();
        if (threadIdx.x < 3) {
            float s = 0.f;
            #pragma unroll
            for (int k = 0; k < TPB / 32; k++) s += sm7[threadIdx.x][k];
            g_part[t * 3 + threadIdx.x] = s;
        }
        if (threadIdx.x == 0) {
            g_neqp[t * 3 + 0] = nq1;
            g_neqp[t * 3 + 1] = nq2;
            g_neqp[t * 3 + 2] = nq3;
        }
    }

    // ---------------- elect last-finished block for the epilogue ----------
    __syncthreads();
    if (threadIdx.x == 0) {
        __threadfence();
        int old = atomicAdd(&g_ctr, 1);
        s_last = (old == NBLOCKS - 1) ? 1 : 0;
    }
    __syncthreads();
    if (!s_last) return;

    __threadfence();  // acquire: make all other blocks' writes visible

    // thread t handles batch t (256 threads == NB)
    const int b = threadIdx.x;
    float pen = 0.0f;
    {
        const float outw = out[1 + b];   // cond ? wgt : 0
        #pragma unroll
        for (int j = 0; j < 3; j++) {
            float dsq = 0.f;
            int nq = 0;
            #pragma unroll
            for (int c = 0; c < TILES_PER_B; c++) {
                dsq += g_part[(b * TILES_PER_B + c) * 3 + j];
                nq |= g_neqp[(b * TILES_PER_B + c) * 3 + j];
            }
            float img_diff = sqrtf(dsq) + 1e-10f;
            float ratio = (1.0f - g_cos[b * 3 + j]) / img_diff;  // LIP = 0
            float term = fmaxf(ratio, 0.0f) * outw;              // SQUARED = false
            if (nq) pen += term;                                 // outw==0 covers !cond
        }
    }
    #pragma unroll
    for (int off = 16; off; off >>= 1)
        pen += __shfl_down_sync(0xffffffffu, pen, off);
    if (l == 0) smr[w] = pen;
    __syncthreads();
    if (threadIdx.x == 0) {
        float s = 0.f;
        #pragma unroll
        for (int k = 0; k < TPB / 32; k++) s += smr[k];
        out[0] = s * (1.0f / (float)NB);   // LAMB_LIP = 1
        g_ctr = 0;                          // reset for next graph replay
    }
}

extern "C" void kernel_launch(void* const* d_in, const int* in_sizes, int n_in,
                              void* d_out, int out_size) {
    const float4* img = (const float4*)d_in[0];
    const float* feat = (const float*)d_in[1];
    const float* feat_norm = (const float*)d_in[2];
    float* out = (float*)d_out;

    fused_kernel<<<NBLOCKS, TPB>>>(img, feat, feat_norm, out);
}

// round 4
// speedup vs baseline: 1.1950x; 1.1479x over previous
#include <cuda_runtime.h>
#include <math.h>

// Shapes
#define NB 256            // batch
#define NF 4              // frames
#define PIX4 9408         // float4 per frame (3*112*112/4)
#define TILES_PER_B 4
#define NTILES (NB * TILES_PER_B)       // 1024 img tiles
#define TILE4 (PIX4 / TILES_PER_B)      // 2352 float4 per tile
#define TPB 256
#define NBLOCKS (NB + NTILES)           // 256 feat blocks + 1024 img blocks

// Scratch: written exactly once per slot per launch — no zeroing needed.
__device__ float g_part[NTILES * 3];    // per-tile squared-diff partials
__device__ int   g_neqp[NTILES * 3];    // per-tile any-neq flags
__device__ float g_cos[NB * 3];         // per-batch cosine similarities
__device__ int   g_ctr;                 // zero at process start; reset by epilogue

__device__ __forceinline__ void accum_group(const float4& f0, const float4& f1,
                                            const float4& f2, const float4& f3,
                                            float& s1, float& s2, float& s3,
                                            int& nq1, int& nq2, int& nq3) {
    float dx, dy, dz, dw;
    dx = f1.x - f0.x; dy = f1.y - f0.y; dz = f1.z - f0.z; dw = f1.w - f0.w;
    s1 += dx * dx + dy * dy + dz * dz + dw * dw;
    nq1 |= (f1.x != f0.x) | (f1.y != f0.y) | (f1.z != f0.z) | (f1.w != f0.w);

    dx = f2.x - f1.x; dy = f2.y - f1.y; dz = f2.z - f1.z; dw = f2.w - f1.w;
    s2 += dx * dx + dy * dy + dz * dz + dw * dw;
    nq2 |= (f2.x != f0.x) | (f2.y != f0.y) | (f2.z != f0.z) | (f2.w != f0.w);

    dx = f3.x - f2.x; dy = f3.y - f2.y; dz = f3.z - f2.z; dw = f3.w - f2.w;
    s3 += dx * dx + dy * dy + dz * dz + dw * dw;
    nq3 |= (f3.x != f0.x) | (f3.y != f0.y) | (f3.z != f0.z) | (f3.w != f0.w);
}

__global__ void fused_kernel(const float4* __restrict__ img,
                             const float* __restrict__ feat,
                             const float* __restrict__ feat_norm,
                             float* __restrict__ out) {
    __shared__ float sm7[7][TPB / 32];
    __shared__ int   smn[TPB / 32];
    __shared__ float smr[TPB / 32];
    __shared__ int   s_last;

    const int w = threadIdx.x >> 5;
    const int l = threadIdx.x & 31;

    if (blockIdx.x < NB) {
        // ---------------- feat block: per-batch norms/dots/cos + weight ----
        const int b = blockIdx.x;
        const float* fb = feat + (size_t)b * (NF * 512);

        float n0 = 0.f, n1 = 0.f, n2 = 0.f, n3 = 0.f;
        float d01 = 0.f, d12 = 0.f, d23 = 0.f;
        #pragma unroll
        for (int k = 0; k < 2; k++) {
            int i = threadIdx.x + k * TPB;
            float a = fb[i];
            float c = fb[512 + i];
            float d = fb[1024 + i];
            float e = fb[1536 + i];
            n0 += a * a; n1 += c * c; n2 += d * d; n3 += e * e;
            d01 += a * c; d12 += c * d; d23 += d * e;
        }
        #pragma unroll
        for (int off = 16; off; off >>= 1) {
            n0  += __shfl_down_sync(0xffffffffu, n0,  off);
            n1  += __shfl_down_sync(0xffffffffu, n1,  off);
            n2  += __shfl_down_sync(0xffffffffu, n2,  off);
            n3  += __shfl_down_sync(0xffffffffu, n3,  off);
            d01 += __shfl_down_sync(0xffffffffu, d01, off);
            d12 += __shfl_down_sync(0xffffffffu, d12, off);
            d23 += __shfl_down_sync(0xffffffffu, d23, off);
        }
        if (l == 0) {
            sm7[0][w] = n0;  sm7[1][w] = n1;  sm7[2][w] = n2;  sm7[3][w] = n3;
            sm7[4][w] = d01; sm7[5][w] = d12; sm7[6][w] = d23;
        }
        __syncthreads();
        if (threadIdx.x == 0) {
            float v[7];
            #pragma unroll
            for (int j = 0; j < 7; j++) {
                float s = 0.f;
                #pragma unroll
                for (int k = 0; k < TPB / 32; k++) s += sm7[j][k];
                v[j] = s;
            }
            float na[4];
            #pragma unroll
            for (int j = 0; j < 4; j++) na[j] = fmaxf(sqrtf(v[j]), 1e-8f);
            #pragma unroll
            for (int j = 0; j < 3; j++)
                g_cos[b * 3 + j] = v[4 + j] / (na[j] * na[j + 1]);

            const float fn0 = feat_norm[b * NF];     // feat_norm[b,0,0]
            const bool cond = fn0 > 0.0f;            // TAO = 0
            const float wgt = 1.0f / (expf(fn0) + 1e-10f);
            out[1 + b] = cond ? wgt : 0.0f;          // wgt>0 always -> also encodes cond
        }
    } else {
        // ---------------- img tile block: squared diffs + neq flags --------
        const int t = blockIdx.x - NB;               // tile index
        const int b = t >> 2;
        const int chunk = t & 3;
        const float4* base = img + (size_t)b * (NF * PIX4);

        float s1 = 0.f, s2 = 0.f, s3 = 0.f;
        int nq1 = 0, nq2 = 0, nq3 = 0;
        const int end = (chunk + 1) * TILE4;

        // 2x unrolled: batch 8 independent LDG.128 before any compute.
        for (int i = chunk * TILE4 + threadIdx.x; i < end; i += 2 * TPB) {
            const int i2 = i + TPB;
            const bool has2 = i2 < end;

            float4 a0 = __ldcs(base + i);
            float4 a1 = __ldcs(base + PIX4 + i);
            float4 a2 = __ldcs(base + 2 * PIX4 + i);
            float4 a3 = __ldcs(base + 3 * PIX4 + i);
            float4 b0, b1, b2, b3;
            if (has2) {
                b0 = __ldcs(base + i2);
                b1 = __ldcs(base + PIX4 + i2);
                b2 = __ldcs(base + 2 * PIX4 + i2);
                b3 = __ldcs(base + 3 * PIX4 + i2);
            }

            accum_group(a0, a1, a2, a3, s1, s2, s3, nq1, nq2, nq3);
            if (has2)
                accum_group(b0, b1, b2, b3, s1, s2, s3, nq1, nq2, nq3);
        }

        // Single fused reduction: 3 float sums + packed neq bits.
        int nqp = nq1 | (nq2 << 1) | (nq3 << 2);
        #pragma unroll
        for (int off = 16; off; off >>= 1) {
            s1 += __shfl_down_sync(0xffffffffu, s1, off);
            s2 += __shfl_down_sync(0xffffffffu, s2, off);
            s3 += __shfl_down_sync(0xffffffffu, s3, off);
            nqp |= __shfl_down_sync(0xffffffffu, nqp, off);
        }
        if (l == 0) { sm7[0][w] = s1; sm7[1][w] = s2; sm7[2][w] = s3; smn[w] = nqp; }
        __syncthreads();
        if (threadIdx.x < 3) {
            float s = 0.f;
            int nq = 0;
            #pragma unroll
            for (int k = 0; k < TPB / 32; k++) { s += sm7[threadIdx.x][k]; nq |= smn[k]; }
            g_part[t * 3 + threadIdx.x] = s;
            g_neqp[t * 3 + threadIdx.x] = (nq >> threadIdx.x) & 1;
        }
    }

    // ---------------- elect last-finished block for the epilogue ----------
    __syncthreads();
    if (threadIdx.x == 0) {
        __threadfence();
        int old = atomicAdd(&g_ctr, 1);
        s_last = (old == NBLOCKS - 1) ? 1 : 0;
    }
    __syncthreads();
    if (!s_last) return;

    __threadfence();  // acquire: make all other blocks' writes visible

    // thread t handles batch t (256 threads == NB)
    const int b = threadIdx.x;
    float pen = 0.0f;
    {
        const float outw = out[1 + b];   // cond ? wgt : 0
        #pragma unroll
        for (int j = 0; j < 3; j++) {
            float dsq = 0.f;
            int nq = 0;
            #pragma unroll
            for (int c = 0; c < TILES_PER_B; c++) {
                dsq += g_part[(b * TILES_PER_B + c) * 3 + j];
                nq |= g_neqp[(b * TILES_PER_B + c) * 3 + j];
            }
            float img_diff = sqrtf(dsq) + 1e-10f;
            float ratio = (1.0f - g_cos[b * 3 + j]) / img_diff;  // LIP = 0
            float term = fmaxf(ratio, 0.0f) * outw;              // SQUARED = false
            if (nq) pen += term;                                 // outw==0 covers !cond
        }
    }
    #pragma unroll
    for (int off = 16; off; off >>= 1)
        pen += __shfl_down_sync(0xffffffffu, pen, off);
    if (l == 0) smr[w] = pen;
    __syncthreads();
    if (threadIdx.x == 0) {
        float s = 0.f;
        #pragma unroll
        for (int k = 0; k < TPB / 32; k++) s += smr[k];
        out[0] = s * (1.0f / (float)NB);   // LAMB_LIP = 1
        g_ctr = 0;                          // reset for next graph replay
    }
}

extern "C" void kernel_launch(void* const* d_in, const int* in_sizes, int n_in,
                              void* d_out, int out_size) {
    const float4* img = (const float4*)d_in[0];
    const float* feat = (const float*)d_in[1];
    const float* feat_norm = (const float*)d_in[2];
    float* out = (float*)d_out;

    fused_kernel<<<NBLOCKS, TPB>>>(img, feat, feat_norm, out);
}